// round 16
// baseline (speedup 1.0000x reference)
#include <cuda_runtime.h>
#include <cuda_bf16.h>
#include <math.h>
#include <stdint.h>

// ---------------------------------------------------------------- constants
#define NN 100000
#define DD 512
#define KK 256
#define RB1 782                 // ceil(NN/128) row-blocks
#define NCT 1591                // n-chunks of 64: NPAD = 101824 = 37*43*64
#define NPAD (NCT * 64)
#define S2 37
#define NC2 43                  // chunks per GEMM2 split
#define ZBLK 480                // zero-fill blocks appended to norm grid

// stage layout (bytes, within one buffer): Ah 16K | Al 16K | Bh 32K | Bl 32K
#define OFF_AL 16384
#define OFF_BH 32768
#define OFF_BL 65536
#define STAGE 98304
#define STAGE_TX 98304
#define OFF_BUF 8192
#define SMEM_TOT (OFF_BUF + 2 * STAGE)    // 204800

// ---------------------------------------------------------------- globals
__device__ __nv_bfloat16 g_dhi[(size_t)RB1 * 8 * 8192];    // tiled 128x64 sw
__device__ __nv_bfloat16 g_dlo[(size_t)RB1 * 8 * 8192];
__device__ __nv_bfloat16 g_dThi[(size_t)2 * NCT * 16384];  // tiled 256x64 sw
__device__ __nv_bfloat16 g_dTlo[(size_t)2 * NCT * 16384];
__device__ __nv_bfloat16 g_rThi[(size_t)2 * NCT * 8192];   // tiled 128x64 sw
__device__ __nv_bfloat16 g_rTlo[(size_t)2 * NCT * 8192];
__device__ __nv_bfloat16 g_muhi[8 * 16384];                // tiled 256x64 sw
__device__ __nv_bfloat16 g_mulo[8 * 16384];
__device__ float g_mu[KK * DD];
__device__ float g_part[S2][KK * DD];
__device__ float g_rsum_part[RB1][KK];

// ---------------------------------------------------------------- asm helpers
__device__ __forceinline__ uint32_t smem_u32(const void* p) {
    uint32_t a;
    asm("{ .reg .u64 t; cvta.to.shared.u64 t, %1; cvt.u32.u64 %0, t; }" : "=r"(a) : "l"(p));
    return a;
}
__device__ __forceinline__ uint32_t swz(uint32_t bo) { return bo ^ ((bo >> 3) & 0x70); }

__device__ __forceinline__ void bulk_ld(uint32_t dst, const void* src, int bytes, uint32_t mb) {
    asm volatile(
        "cp.async.bulk.shared::cta.global.mbarrier::complete_tx::bytes [%0], [%1], %2, [%3];"
        :: "r"(dst), "l"(src), "r"(bytes), "r"(mb) : "memory");
}
__device__ __forceinline__ void bulk_st(void* dst, uint32_t src, int bytes) {
    asm volatile("cp.async.bulk.global.shared::cta.bulk_group [%0], [%1], %2;"
                 :: "l"(dst), "r"(src), "r"(bytes) : "memory");
}
#define BULK_COMMIT() asm volatile("cp.async.bulk.commit_group;" ::: "memory")
#define BULK_WAIT0()  asm volatile("cp.async.bulk.wait_group 0;" ::: "memory")
#define MB_INIT(mb, n) asm volatile("mbarrier.init.shared.b64 [%0], %1;" :: "r"((uint32_t)(mb)), "r"((uint32_t)(n)) : "memory")
#define MB_EXPECT(mb, tx) asm volatile("mbarrier.arrive.expect_tx.shared.b64 _, [%0], %1;" :: "r"((uint32_t)(mb)), "r"((uint32_t)(tx)) : "memory")
#define FENCE_ASYNC() asm volatile("fence.proxy.async.shared::cta;" ::: "memory")

__device__ __forceinline__ void mbar_wait(uint32_t mb, int par) {
    asm volatile(
        "{\n\t.reg .pred P;\n\t"
        "WL_%=:\n\t"
        "mbarrier.try_wait.parity.acquire.cta.shared::cta.b64 P, [%0], %1, 0x989680;\n\t"
        "@P bra.uni WD_%=;\n\t"
        "bra.uni WL_%=;\n\t"
        "WD_%=:\n\t}"
        :: "r"(mb), "r"((uint32_t)par) : "memory");
}

__device__ __forceinline__ void ldm4(uint32_t* r, uint32_t addr) {
    asm volatile("ldmatrix.sync.aligned.m8n8.x4.shared.b16 {%0,%1,%2,%3}, [%4];"
                 : "=r"(r[0]), "=r"(r[1]), "=r"(r[2]), "=r"(r[3]) : "r"(addr));
}
__device__ __forceinline__ void mma16816(float* c, const uint32_t* a,
                                         uint32_t b0, uint32_t b1) {
    asm volatile(
        "mma.sync.aligned.m16n8k16.row.col.f32.bf16.bf16.f32 "
        "{%0,%1,%2,%3},{%4,%5,%6,%7},{%8,%9},{%0,%1,%2,%3};"
        : "+f"(c[0]), "+f"(c[1]), "+f"(c[2]), "+f"(c[3])
        : "r"(a[0]), "r"(a[1]), "r"(a[2]), "r"(a[3]), "r"(b0), "r"(b1));
}

// warp tile 32(M) x 64(N) over one 64-contraction chunk; 3-product bf16 split.
// Product-major ordering: consecutive HMMAs hit DIFFERENT accumulators so the
// tensor pipe never stalls on a same-acc RAW chain.
__device__ __forceinline__ void mma_chunk(uint32_t st, float acc[2][8][4],
                                          int lane, int wm, int wn) {
    const int lrow = lane & 15;
    const int lkb = (lane >> 4) * 16;
    #pragma unroll
    for (int ks = 0; ks < 4; ks++) {
        const int kb = ks * 32 + lkb;
        uint32_t ah[2][4], al[2][4];
        #pragma unroll
        for (int i = 0; i < 2; i++) {
            uint32_t swo = swz((uint32_t)(wm * 32 + i * 16 + lrow) * 128 + kb);
            ldm4(ah[i], st + swo);
            ldm4(al[i], st + OFF_AL + swo);
        }
        #pragma unroll
        for (int j2 = 0; j2 < 4; j2++) {
            uint32_t swo = swz((uint32_t)(wn * 64 + j2 * 16 + lrow) * 128 + kb);
            uint32_t bh[4], bl[4];
            ldm4(bh, st + OFF_BH + swo);
            ldm4(bl, st + OFF_BL + swo);
            #pragma unroll
            for (int p = 0; p < 3; p++) {
                #pragma unroll
                for (int i = 0; i < 2; i++) {
                    #pragma unroll
                    for (int h = 0; h < 2; h++) {
                        float* c = acc[i][j2 * 2 + h];
                        const uint32_t* a = (p == 2) ? al[i] : ah[i];
                        uint32_t b0 = (p == 1) ? bl[h] : bh[h];
                        uint32_t b1 = (p == 1) ? bl[h + 2] : bh[h + 2];
                        mma16816(c, a, b0, b1);
                    }
                }
            }
        }
    }
}

// ---------------------------------------------------------------- small kernels
__device__ __forceinline__ float block_sumsq_512(float4 v) {
    float ss = v.x * v.x + v.y * v.y + v.z * v.z + v.w * v.w;
    #pragma unroll
    for (int off = 16; off > 0; off >>= 1)
        ss += __shfl_xor_sync(0xffffffffu, ss, off);
    __shared__ float wsum[4];
    if ((threadIdx.x & 31) == 0) wsum[threadIdx.x >> 5] = ss;
    __syncthreads();
    return wsum[0] + wsum[1] + wsum[2] + wsum[3];
}

__device__ __forceinline__ void split_store(char* basehi, char* baselo,
                                            size_t byteoff, const float* x) {
    __nv_bfloat16 h[4], l[4];
    #pragma unroll
    for (int i = 0; i < 4; i++) {
        h[i] = __float2bfloat16(x[i]);
        l[i] = __float2bfloat16(x[i] - __bfloat162float(h[i]));
    }
    *(uint2*)(basehi + byteoff) = *(const uint2*)h;
    *(uint2*)(baselo + byteoff) = *(const uint2*)l;
}

// normalize data rows -> tiled swizzled hi/lo; tail blocks zero pad regions.
__global__ void k_norm_split(const float* __restrict__ in) {
    if (blockIdx.x >= NN) {
        int id = (int)(blockIdx.x - NN) * 128 + threadIdx.x;   // 0..61439
        const uint4 z = make_uint4(0, 0, 0, 0);
        if (id < 6144) {
            int kc = id / 768, off16 = id - kc * 768;
            size_t bo = (size_t)(781 * 8 + kc) * 16384 + 4096 + (size_t)off16 * 16;
            *(uint4*)((char*)g_dhi + bo) = z;
            *(uint4*)((char*)g_dlo + bo) = z;
        } else {
            int id2 = id - 6144;                 // 0..55295
            int mt = id2 / 27648, rem = id2 - mt * 27648;
            int nc2 = 1564 + rem / 1024, off16 = rem & 1023;
            size_t bo = ((size_t)mt * NCT + nc2) * 16384 + (size_t)off16 * 16;
            *(uint4*)((char*)g_rThi + bo) = z;
            *(uint4*)((char*)g_rTlo + bo) = z;
        }
        return;
    }
    size_t row = blockIdx.x;
    float4 v = ((const float4*)(in + row * DD))[threadIdx.x];
    float tot = block_sumsq_512(v);
    float inv = 1.0f / (sqrtf(tot) + 1e-6f);
    float x[4] = {v.x * inv, v.y * inv, v.z * inv, v.w * inv};
    int d = threadIdx.x * 4;
    int rb = (int)(row >> 7), rr = (int)(row & 127), kc = d >> 6;
    size_t bo = (size_t)(rb * 8 + kc) * 16384 + swz((uint32_t)rr * 128 + (d & 63) * 2);
    split_store((char*)g_dhi, (char*)g_dlo, bo, x);
}

// normalize mu row -> tiled swizzled hi/lo (B tiles: 256x64); iter 0 reads init
__global__ void k_norm_mu(const float* __restrict__ initp, int use_init) {
    size_t row = blockIdx.x;
    const float* src = use_init ? initp : g_mu;
    float4 v = ((const float4*)(src + row * DD))[threadIdx.x];
    float tot = block_sumsq_512(v);
    float inv = 1.0f / (sqrtf(tot) + 1e-6f);
    float x[4] = {v.x * inv, v.y * inv, v.z * inv, v.w * inv};
    int d = threadIdx.x * 4;
    int kc = d >> 6;
    size_t bo = (size_t)kc * 32768 + swz((uint32_t)row * 128 + (d & 63) * 2);
    split_store((char*)g_muhi, (char*)g_mulo, bo, x);
}

// build dataT tiles (256 d-rows x 64 n-cols, swizzled); 16B gmem both sides
__global__ void k_transpose() {
    __shared__ __nv_bfloat16 th[64][72];
    __shared__ __nv_bfloat16 tl[64][72];
    int nc = blockIdx.x, nt = blockIdx.y;
    int tid = threadIdx.x;
    int rb = nc >> 1, nb = (nc & 1) * 64;
    for (int sub = 0; sub < 4; sub++) {
        int kc = nt * 4 + sub;
        #pragma unroll
        for (int e = 0; e < 2; e++) {
            int id = tid + e * 256;              // 0..511
            int rn = id >> 3, d8 = id & 7;
            uint4 vh = make_uint4(0, 0, 0, 0), vl = make_uint4(0, 0, 0, 0);
            if (nc < 1564) {
                size_t bo = (size_t)(rb * 8 + kc) * 16384 +
                            swz((uint32_t)(nb + rn) * 128 + d8 * 16);
                vh = *(const uint4*)((const char*)g_dhi + bo);
                vl = *(const uint4*)((const char*)g_dlo + bo);
            }
            *(uint4*)&th[rn][d8 * 8] = vh;
            *(uint4*)&tl[rn][d8 * 8] = vl;
        }
        __syncthreads();
        #pragma unroll
        for (int e = 0; e < 2; e++) {
            int id = tid + e * 256;
            int dr = id >> 3, n8 = id & 7;
            __nv_bfloat16 ph[8], pl[8];
            #pragma unroll
            for (int j = 0; j < 8; j++) {
                ph[j] = th[n8 * 8 + j][dr];
                pl[j] = tl[n8 * 8 + j][dr];
            }
            size_t bo = ((size_t)nt * NCT + nc) * 32768 +
                        swz((uint32_t)(sub * 64 + dr) * 128 + n8 * 16);
            *(uint4*)((char*)g_dThi + bo) = *(uint4*)ph;
            *(uint4*)((char*)g_dTlo + bo) = *(uint4*)pl;
        }
        __syncthreads();
    }
}

// ---------------------------------------------------------------- GEMM1 + softmax
// block: 128 data rows x 256 clusters; 16 warps (4M x 4N), warp 32x64.
__global__ __launch_bounds__(512, 1)
void k_gemm1(const float* __restrict__ tempp, float* __restrict__ rout, int lastit) {
    extern __shared__ char smem[];
    uint32_t sb = smem_u32(smem);
    const int tid = threadIdx.x;
    const int lane = tid & 31, w = tid >> 5;
    const int wm = w >> 2, wn = w & 3;
    const int rb = blockIdx.x;
    const size_t nbase = (size_t)rb * 128;
    const uint32_t mb0 = sb + 8, mb1 = sb + 16;

    float acc[2][8][4] = {};

    auto issue = [&](int c, int buf, uint32_t mb) {
        uint32_t st = sb + OFF_BUF + buf * STAGE;
        MB_EXPECT(mb, STAGE_TX);
        bulk_ld(st,          (const char*)g_dhi + (size_t)(rb * 8 + c) * 16384, 16384, mb);
        bulk_ld(st + OFF_AL, (const char*)g_dlo + (size_t)(rb * 8 + c) * 16384, 16384, mb);
        bulk_ld(st + OFF_BH, (const char*)g_muhi + (size_t)c * 32768, 32768, mb);
        bulk_ld(st + OFF_BL, (const char*)g_mulo + (size_t)c * 32768, 32768, mb);
    };

    if (tid == 0) {
        MB_INIT(mb0, 1);
        MB_INIT(mb1, 1);
        FENCE_ASYNC();
        issue(0, 0, mb0);
        issue(1, 1, mb1);
    }
    __syncthreads();

    int ph0 = 0, ph1 = 0;
    for (int c = 0; c < 8; c++) {
        int buf = c & 1;
        uint32_t mb = buf ? mb1 : mb0;
        if (buf == 0) { mbar_wait(mb0, ph0); ph0 ^= 1; }
        else          { mbar_wait(mb1, ph1); ph1 ^= 1; }
        mma_chunk(sb + OFF_BUF + buf * STAGE, acc, lane, wm, wn);
        __syncthreads();
        if (c + 2 < 8 && tid == 0) { FENCE_ASYNC(); issue(c + 2, buf, mb); }
    }

    // ---------------- softmax epilogue ----------------
    const float tv = tempp[0];
    const int g = lane >> 2, q = lane & 3;
    float* sums = (float*)(smem + 64);      // [128][4]
    float* colsum4 = (float*)(smem + 2112); // [4][256]

    #pragma unroll
    for (int i = 0; i < 2; i++)
        #pragma unroll
        for (int jn = 0; jn < 8; jn++)
            #pragma unroll
            for (int r = 0; r < 4; r++)
                acc[i][jn][r] = __expf(tv * acc[i][jn][r]);

    #pragma unroll
    for (int i = 0; i < 2; i++) {
        #pragma unroll
        for (int h = 0; h < 2; h++) {
            float p = 0.f;
            #pragma unroll
            for (int jn = 0; jn < 8; jn++)
                p += acc[i][jn][h * 2] + acc[i][jn][h * 2 + 1];
            p += __shfl_xor_sync(0xffffffffu, p, 1);
            p += __shfl_xor_sync(0xffffffffu, p, 2);
            if (q == 0) {
                int rr = wm * 32 + i * 16 + h * 8 + g;
                sums[rr * 4 + wn] = p;
            }
        }
    }
    __syncthreads();

    // write rT tiles into SMEM; accumulate per-thread column sums
    char* tb = smem + OFF_BUF;
    float cs[8][2];
    #pragma unroll
    for (int jn = 0; jn < 8; jn++) { cs[jn][0] = 0.f; cs[jn][1] = 0.f; }

    #pragma unroll
    for (int i = 0; i < 2; i++) {
        #pragma unroll
        for (int h = 0; h < 2; h++) {
            int rr = wm * 32 + i * 16 + h * 8 + g;
            size_t gr = nbase + rr;
            bool v = gr < NN;
            float inv = 1.0f / (sums[rr * 4 + 0] + sums[rr * 4 + 1] +
                                sums[rr * 4 + 2] + sums[rr * 4 + 3]);
            int ncl = rr >> 6, nn = rr & 63;
            #pragma unroll
            for (int jn = 0; jn < 8; jn++) {
                #pragma unroll
                for (int cc = 0; cc < 2; cc++) {
                    float e = v ? acc[i][jn][h * 2 + cc] * inv : 0.f;
                    cs[jn][cc] += e;
                    int k = wn * 64 + jn * 8 + q * 2 + cc;
                    int mt = k >> 7, kr = k & 127;
                    uint32_t bo = (mt * 2 + ncl) * 16384 + swz((uint32_t)kr * 128 + nn * 2);
                    __nv_bfloat16 hi = __float2bfloat16(e);
                    *(__nv_bfloat16*)(tb + bo) = hi;
                    *(__nv_bfloat16*)(tb + 65536 + bo) =
                        __float2bfloat16(e - __bfloat162float(hi));
                    if (lastit && v) rout[gr * (size_t)KK + k] = e;
                }
            }
        }
    }

    // reduce column sums over the 8 g-lanes (same k across g)
    #pragma unroll
    for (int jn = 0; jn < 8; jn++)
        #pragma unroll
        for (int cc = 0; cc < 2; cc++) {
            float s = cs[jn][cc];
            s += __shfl_xor_sync(0xffffffffu, s, 4);
            s += __shfl_xor_sync(0xffffffffu, s, 8);
            s += __shfl_xor_sync(0xffffffffu, s, 16);
            cs[jn][cc] = s;
        }
    if (lane < 4) {
        #pragma unroll
        for (int jn = 0; jn < 8; jn++)
            #pragma unroll
            for (int cc = 0; cc < 2; cc++)
                colsum4[wm * 256 + wn * 64 + jn * 8 + q * 2 + cc] = cs[jn][cc];
    }
    __syncthreads();
    if (tid < 256) {
        float t = (colsum4[tid] + colsum4[256 + tid]) +
                  (colsum4[512 + tid] + colsum4[768 + tid]);
        g_rsum_part[rb][tid] = t;
    }

    FENCE_ASYNC();
    if (tid < 8) {
        int arr = tid & 1, t = tid >> 1;
        int mt = t >> 1, ncl = t & 1;
        size_t dsto = ((size_t)mt * NCT + (rb * 2 + ncl)) * 16384;
        char* dst = (arr ? (char*)g_rTlo : (char*)g_rThi) + dsto;
        bulk_st(dst, sb + OFF_BUF + t * 16384 + arr * 65536, 16384);
        BULK_COMMIT();
        BULK_WAIT0();
    }
}

// ---------------------------------------------------------------- GEMM2
// block: 128 clusters x 256 d-cols; 16 warps (4M x 4N), warp 32x64.
__global__ __launch_bounds__(512, 1)
void k_gemm2() {
    extern __shared__ char smem[];
    uint32_t sb = smem_u32(smem);
    const int tid = threadIdx.x;
    const int lane = tid & 31, w = tid >> 5;
    const int wm = w >> 2, wn = w & 3;
    const int mt = blockIdx.x, nt = blockIdx.y, sp = blockIdx.z;
    const uint32_t mb0 = sb + 8, mb1 = sb + 16;

    float acc[2][8][4] = {};

    auto issue = [&](int c, int buf, uint32_t mb) {
        uint32_t st = sb + OFF_BUF + buf * STAGE;
        size_t nc = (size_t)sp * NC2 + c;
        MB_EXPECT(mb, STAGE_TX);
        bulk_ld(st,          (const char*)g_rThi + ((size_t)mt * NCT + nc) * 16384, 16384, mb);
        bulk_ld(st + OFF_AL, (const char*)g_rTlo + ((size_t)mt * NCT + nc) * 16384, 16384, mb);
        bulk_ld(st + OFF_BH, (const char*)g_dThi + ((size_t)nt * NCT + nc) * 32768, 32768, mb);
        bulk_ld(st + OFF_BL, (const char*)g_dTlo + ((size_t)nt * NCT + nc) * 32768, 32768, mb);
    };

    if (tid == 0) {
        MB_INIT(mb0, 1);
        MB_INIT(mb1, 1);
        FENCE_ASYNC();
        issue(0, 0, mb0);
        issue(1, 1, mb1);
    }
    __syncthreads();

    int ph0 = 0, ph1 = 0;
    for (int c = 0; c < NC2; c++) {
        int buf = c & 1;
        uint32_t mb = buf ? mb1 : mb0;
        if (buf == 0) { mbar_wait(mb0, ph0); ph0 ^= 1; }
        else          { mbar_wait(mb1, ph1); ph1 ^= 1; }
        mma_chunk(sb + OFF_BUF + buf * STAGE, acc, lane, wm, wn);
        __syncthreads();
        if (c + 2 < NC2 && tid == 0) { FENCE_ASYNC(); issue(c + 2, buf, mb); }
    }

    // epilogue: 128x256 fp32 partial
    const int g = lane >> 2, q = lane & 3;
    float* p = g_part[sp];
    #pragma unroll
    for (int i = 0; i < 2; i++) {
        #pragma unroll
        for (int h = 0; h < 2; h++) {
            int rr = wm * 32 + i * 16 + h * 8 + g;
            float* dst = p + (size_t)(mt * 128 + rr) * DD + nt * 256 + wn * 64;
            #pragma unroll
            for (int jn = 0; jn < 8; jn++) {
                float2 v = make_float2(acc[i][jn][h * 2], acc[i][jn][h * 2 + 1]);
                *(float2*)(dst + jn * 8 + q * 2) = v;
            }
        }
    }
}

// ---------------------------------------------------------------- finalize mu (fused rsum)
// one block per k: 512 threads reduce g_rsum_part[*][k], then sum partials and divide.
__global__ void k_mu_final(float* __restrict__ extout, int write_ext) {
    int k = blockIdx.x;
    int tid = threadIdx.x;
    float rs = 0.f;
    for (int rb = tid; rb < RB1; rb += 512) rs += g_rsum_part[rb][k];
    #pragma unroll
    for (int off = 16; off > 0; off >>= 1)
        rs += __shfl_xor_sync(0xffffffffu, rs, off);
    __shared__ float ws[16];
    __shared__ float rsum_s;
    if ((tid & 31) == 0) ws[tid >> 5] = rs;
    __syncthreads();
    if (tid == 0) {
        float t = 0.f;
        #pragma unroll
        for (int i = 0; i < 16; i++) t += ws[i];
        rsum_s = t;
    }
    __syncthreads();
    float denom = rsum_s;
    int idx = k * DD + tid;
    float s = 0.f;
    #pragma unroll
    for (int p = 0; p < S2; p++) s += g_part[p][idx];
    float v = s / denom;
    g_mu[idx] = v;
    if (write_ext) extout[idx] = v;
}

// ---------------------------------------------------------------- launch
extern "C" void kernel_launch(void* const* d_in, const int* in_sizes, int n_in,
                              void* d_out, int out_size) {
    const float* embeds = (const float*)d_in[0];
    const float* temp   = (const float*)d_in[1];
    const float* init   = (const float*)d_in[2];
    float* out_mu = (float*)d_out;
    float* out_r  = (float*)d_out + KK * DD;

    cudaFuncSetAttribute(k_gemm1, cudaFuncAttributeMaxDynamicSharedMemorySize, SMEM_TOT);
    cudaFuncSetAttribute(k_gemm2, cudaFuncAttributeMaxDynamicSharedMemorySize, SMEM_TOT);

    // launch order keeps k_gemm1 at launch #4 (ncu capture slot)
    k_norm_split<<<NN + ZBLK, 128>>>(embeds);
    k_transpose<<<dim3(NCT, 2), 256>>>();

    for (int it = 0; it < 11; it++) {
        k_norm_mu<<<KK, 128>>>(init, it == 0 ? 1 : 0);
        k_gemm1<<<RB1, 512, SMEM_TOT>>>(temp, out_r, it == 10 ? 1 : 0);
        k_gemm2<<<dim3(2, 2, S2), 512, SMEM_TOT>>>();
        k_mu_final<<<KK, 512>>>(out_mu, it == 10 ? 1 : 0);
    }
}

// round 17
// speedup vs baseline: 1.5395x; 1.5395x over previous
#include <cuda_runtime.h>
#include <cuda_bf16.h>
#include <math.h>
#include <stdint.h>

// ---------------------------------------------------------------- constants
#define NN 100000
#define DD 512
#define KK 256
#define RB1 782                 // ceil(NN/128) row-blocks
#define NCT 1591                // n-chunks of 64: NPAD = 101824 = 37*43*64
#define NPAD (NCT * 64)
#define S2 37
#define NC2 43                  // chunks per GEMM2 split
#define ZBLK 480                // zero-fill blocks appended to norm grid

// stage layout (bytes, within one buffer): Ah 16K | Al 16K | Bh 32K | Bl 32K
#define OFF_AL 16384
#define OFF_BH 32768
#define OFF_BL 65536
#define STAGE 98304
#define STAGE_TX 98304
#define OFF_BUF 8192
#define SMEM_TOT (OFF_BUF + 2 * STAGE)    // 204800

// ---------------------------------------------------------------- globals
__device__ __nv_bfloat16 g_dhi[(size_t)RB1 * 8 * 8192];    // tiled 128x64 sw
__device__ __nv_bfloat16 g_dlo[(size_t)RB1 * 8 * 8192];
__device__ __nv_bfloat16 g_dThi[(size_t)2 * NCT * 16384];  // tiled 256x64 sw
__device__ __nv_bfloat16 g_dTlo[(size_t)2 * NCT * 16384];
__device__ __nv_bfloat16 g_rThi[(size_t)2 * NCT * 8192];   // tiled 128x64 sw
__device__ __nv_bfloat16 g_rTlo[(size_t)2 * NCT * 8192];
__device__ __nv_bfloat16 g_muhi[8 * 16384];                // tiled 256x64 sw
__device__ __nv_bfloat16 g_mulo[8 * 16384];
__device__ float g_mu[KK * DD];
__device__ float g_part[S2][KK * DD];
__device__ float g_rsum_part[RB1][KK];

// ---------------------------------------------------------------- asm helpers
__device__ __forceinline__ uint32_t smem_u32(const void* p) {
    uint32_t a;
    asm("{ .reg .u64 t; cvta.to.shared.u64 t, %1; cvt.u32.u64 %0, t; }" : "=r"(a) : "l"(p));
    return a;
}
__device__ __forceinline__ uint32_t swz(uint32_t bo) { return bo ^ ((bo >> 3) & 0x70); }

__device__ __forceinline__ void bulk_ld(uint32_t dst, const void* src, int bytes, uint32_t mb) {
    asm volatile(
        "cp.async.bulk.shared::cta.global.mbarrier::complete_tx::bytes [%0], [%1], %2, [%3];"
        :: "r"(dst), "l"(src), "r"(bytes), "r"(mb) : "memory");
}
__device__ __forceinline__ void bulk_st(void* dst, uint32_t src, int bytes) {
    asm volatile("cp.async.bulk.global.shared::cta.bulk_group [%0], [%1], %2;"
                 :: "l"(dst), "r"(src), "r"(bytes) : "memory");
}
#define BULK_COMMIT() asm volatile("cp.async.bulk.commit_group;" ::: "memory")
#define BULK_WAIT0()  asm volatile("cp.async.bulk.wait_group 0;" ::: "memory")
#define MB_INIT(mb, n) asm volatile("mbarrier.init.shared.b64 [%0], %1;" :: "r"((uint32_t)(mb)), "r"((uint32_t)(n)) : "memory")
#define MB_EXPECT(mb, tx) asm volatile("mbarrier.arrive.expect_tx.shared.b64 _, [%0], %1;" :: "r"((uint32_t)(mb)), "r"((uint32_t)(tx)) : "memory")
#define FENCE_ASYNC() asm volatile("fence.proxy.async.shared::cta;" ::: "memory")

__device__ __forceinline__ void mbar_wait(uint32_t mb, int par) {
    asm volatile(
        "{\n\t.reg .pred P;\n\t"
        "WL_%=:\n\t"
        "mbarrier.try_wait.parity.acquire.cta.shared::cta.b64 P, [%0], %1, 0x989680;\n\t"
        "@P bra.uni WD_%=;\n\t"
        "bra.uni WL_%=;\n\t"
        "WD_%=:\n\t}"
        :: "r"(mb), "r"((uint32_t)par) : "memory");
}

__device__ __forceinline__ void ldm4(uint32_t* r, uint32_t addr) {
    asm volatile("ldmatrix.sync.aligned.m8n8.x4.shared.b16 {%0,%1,%2,%3}, [%4];"
                 : "=r"(r[0]), "=r"(r[1]), "=r"(r[2]), "=r"(r[3]) : "r"(addr));
}
__device__ __forceinline__ void mma16816(float* c, const uint32_t* a,
                                         uint32_t b0, uint32_t b1) {
    asm volatile(
        "mma.sync.aligned.m16n8k16.row.col.f32.bf16.bf16.f32 "
        "{%0,%1,%2,%3},{%4,%5,%6,%7},{%8,%9},{%0,%1,%2,%3};"
        : "+f"(c[0]), "+f"(c[1]), "+f"(c[2]), "+f"(c[3])
        : "r"(a[0]), "r"(a[1]), "r"(a[2]), "r"(a[3]), "r"(b0), "r"(b1));
}

// warp tile 32(M) x 64(N) over one 64-contraction chunk; 3-product bf16 split.
// R15 champion form: acc-major inner order, compiler-scheduled.
__device__ __forceinline__ void mma_chunk(uint32_t st, float acc[2][8][4],
                                          int lane, int wm, int wn) {
    const int lrow = lane & 15;
    const int lkb = (lane >> 4) * 16;
    #pragma unroll
    for (int ks = 0; ks < 4; ks++) {
        const int kb = ks * 32 + lkb;
        uint32_t ah[2][4], al[2][4];
        #pragma unroll
        for (int i = 0; i < 2; i++) {
            uint32_t swo = swz((uint32_t)(wm * 32 + i * 16 + lrow) * 128 + kb);
            ldm4(ah[i], st + swo);
            ldm4(al[i], st + OFF_AL + swo);
        }
        #pragma unroll
        for (int j2 = 0; j2 < 4; j2++) {
            uint32_t swo = swz((uint32_t)(wn * 64 + j2 * 16 + lrow) * 128 + kb);
            uint32_t bh[4], bl[4];
            ldm4(bh, st + OFF_BH + swo);
            ldm4(bl, st + OFF_BL + swo);
            #pragma unroll
            for (int i = 0; i < 2; i++) {
                #pragma unroll
                for (int h = 0; h < 2; h++) {
                    float* c = acc[i][j2 * 2 + h];
                    mma16816(c, ah[i], bh[h], bh[h + 2]);
                    mma16816(c, ah[i], bl[h], bl[h + 2]);
                    mma16816(c, al[i], bh[h], bh[h + 2]);
                }
            }
        }
    }
}

// ---------------------------------------------------------------- small kernels
__device__ __forceinline__ float block_sumsq_512(float4 v) {
    float ss = v.x * v.x + v.y * v.y + v.z * v.z + v.w * v.w;
    #pragma unroll
    for (int off = 16; off > 0; off >>= 1)
        ss += __shfl_xor_sync(0xffffffffu, ss, off);
    __shared__ float wsum[4];
    if ((threadIdx.x & 31) == 0) wsum[threadIdx.x >> 5] = ss;
    __syncthreads();
    return wsum[0] + wsum[1] + wsum[2] + wsum[3];
}

__device__ __forceinline__ void split_store(char* basehi, char* baselo,
                                            size_t byteoff, const float* x) {
    __nv_bfloat16 h[4], l[4];
    #pragma unroll
    for (int i = 0; i < 4; i++) {
        h[i] = __float2bfloat16(x[i]);
        l[i] = __float2bfloat16(x[i] - __bfloat162float(h[i]));
    }
    *(uint2*)(basehi + byteoff) = *(const uint2*)h;
    *(uint2*)(baselo + byteoff) = *(const uint2*)l;
}

// normalize data rows -> tiled swizzled hi/lo; tail blocks zero pad regions.
__global__ void k_norm_split(const float* __restrict__ in) {
    if (blockIdx.x >= NN) {
        int id = (int)(blockIdx.x - NN) * 128 + threadIdx.x;   // 0..61439
        const uint4 z = make_uint4(0, 0, 0, 0);
        if (id < 6144) {
            int kc = id / 768, off16 = id - kc * 768;
            size_t bo = (size_t)(781 * 8 + kc) * 16384 + 4096 + (size_t)off16 * 16;
            *(uint4*)((char*)g_dhi + bo) = z;
            *(uint4*)((char*)g_dlo + bo) = z;
        } else {
            int id2 = id - 6144;                 // 0..55295
            int mt = id2 / 27648, rem = id2 - mt * 27648;
            int nc2 = 1564 + rem / 1024, off16 = rem & 1023;
            size_t bo = ((size_t)mt * NCT + nc2) * 16384 + (size_t)off16 * 16;
            *(uint4*)((char*)g_rThi + bo) = z;
            *(uint4*)((char*)g_rTlo + bo) = z;
        }
        return;
    }
    size_t row = blockIdx.x;
    float4 v = ((const float4*)(in + row * DD))[threadIdx.x];
    float tot = block_sumsq_512(v);
    float inv = 1.0f / (sqrtf(tot) + 1e-6f);
    float x[4] = {v.x * inv, v.y * inv, v.z * inv, v.w * inv};
    int d = threadIdx.x * 4;
    int rb = (int)(row >> 7), rr = (int)(row & 127), kc = d >> 6;
    size_t bo = (size_t)(rb * 8 + kc) * 16384 + swz((uint32_t)rr * 128 + (d & 63) * 2);
    split_store((char*)g_dhi, (char*)g_dlo, bo, x);
}

// normalize mu row -> tiled swizzled hi/lo (B tiles: 256x64); iter 0 reads init
__global__ void k_norm_mu(const float* __restrict__ initp, int use_init) {
    size_t row = blockIdx.x;
    const float* src = use_init ? initp : g_mu;
    float4 v = ((const float4*)(src + row * DD))[threadIdx.x];
    float tot = block_sumsq_512(v);
    float inv = 1.0f / (sqrtf(tot) + 1e-6f);
    float x[4] = {v.x * inv, v.y * inv, v.z * inv, v.w * inv};
    int d = threadIdx.x * 4;
    int kc = d >> 6;
    size_t bo = (size_t)kc * 32768 + swz((uint32_t)row * 128 + (d & 63) * 2);
    split_store((char*)g_muhi, (char*)g_mulo, bo, x);
}

// build dataT tiles (256 d-rows x 64 n-cols, swizzled); 16B gmem both sides
__global__ void k_transpose() {
    __shared__ __nv_bfloat16 th[64][72];
    __shared__ __nv_bfloat16 tl[64][72];
    int nc = blockIdx.x, nt = blockIdx.y;
    int tid = threadIdx.x;
    int rb = nc >> 1, nb = (nc & 1) * 64;
    for (int sub = 0; sub < 4; sub++) {
        int kc = nt * 4 + sub;
        #pragma unroll
        for (int e = 0; e < 2; e++) {
            int id = tid + e * 256;              // 0..511
            int rn = id >> 3, d8 = id & 7;
            uint4 vh = make_uint4(0, 0, 0, 0), vl = make_uint4(0, 0, 0, 0);
            if (nc < 1564) {
                size_t bo = (size_t)(rb * 8 + kc) * 16384 +
                            swz((uint32_t)(nb + rn) * 128 + d8 * 16);
                vh = *(const uint4*)((const char*)g_dhi + bo);
                vl = *(const uint4*)((const char*)g_dlo + bo);
            }
            *(uint4*)&th[rn][d8 * 8] = vh;
            *(uint4*)&tl[rn][d8 * 8] = vl;
        }
        __syncthreads();
        #pragma unroll
        for (int e = 0; e < 2; e++) {
            int id = tid + e * 256;
            int dr = id >> 3, n8 = id & 7;
            __nv_bfloat16 ph[8], pl[8];
            #pragma unroll
            for (int j = 0; j < 8; j++) {
                ph[j] = th[n8 * 8 + j][dr];
                pl[j] = tl[n8 * 8 + j][dr];
            }
            size_t bo = ((size_t)nt * NCT + nc) * 32768 +
                        swz((uint32_t)(sub * 64 + dr) * 128 + n8 * 16);
            *(uint4*)((char*)g_dThi + bo) = *(uint4*)ph;
            *(uint4*)((char*)g_dTlo + bo) = *(uint4*)pl;
        }
        __syncthreads();
    }
}

// ---------------------------------------------------------------- GEMM1 + softmax
// block: 128 data rows x 256 clusters; 16 warps (4M x 4N), warp 32x64.
__global__ __launch_bounds__(512, 1)
void k_gemm1(const float* __restrict__ tempp, float* __restrict__ rout, int lastit) {
    extern __shared__ char smem[];
    uint32_t sb = smem_u32(smem);
    const int tid = threadIdx.x;
    const int lane = tid & 31, w = tid >> 5;
    const int wm = w >> 2, wn = w & 3;
    const int rb = blockIdx.x;
    const size_t nbase = (size_t)rb * 128;
    const uint32_t mb0 = sb + 8, mb1 = sb + 16;

    float acc[2][8][4] = {};

    auto issue = [&](int c, int buf, uint32_t mb) {
        uint32_t st = sb + OFF_BUF + buf * STAGE;
        MB_EXPECT(mb, STAGE_TX);
        bulk_ld(st,          (const char*)g_dhi + (size_t)(rb * 8 + c) * 16384, 16384, mb);
        bulk_ld(st + OFF_AL, (const char*)g_dlo + (size_t)(rb * 8 + c) * 16384, 16384, mb);
        bulk_ld(st + OFF_BH, (const char*)g_muhi + (size_t)c * 32768, 32768, mb);
        bulk_ld(st + OFF_BL, (const char*)g_mulo + (size_t)c * 32768, 32768, mb);
    };

    if (tid == 0) {
        MB_INIT(mb0, 1);
        MB_INIT(mb1, 1);
        FENCE_ASYNC();
        issue(0, 0, mb0);
        issue(1, 1, mb1);
    }
    __syncthreads();

    int ph0 = 0, ph1 = 0;
    for (int c = 0; c < 8; c++) {
        int buf = c & 1;
        uint32_t mb = buf ? mb1 : mb0;
        if (buf == 0) { mbar_wait(mb0, ph0); ph0 ^= 1; }
        else          { mbar_wait(mb1, ph1); ph1 ^= 1; }
        mma_chunk(sb + OFF_BUF + buf * STAGE, acc, lane, wm, wn);
        __syncthreads();
        if (c + 2 < 8 && tid == 0) { FENCE_ASYNC(); issue(c + 2, buf, mb); }
    }

    // ---------------- softmax epilogue ----------------
    const float tv = tempp[0];
    const int g = lane >> 2, q = lane & 3;
    float* sums = (float*)(smem + 64);      // [128][4]
    float* colsum4 = (float*)(smem + 2112); // [4][256]

    #pragma unroll
    for (int i = 0; i < 2; i++)
        #pragma unroll
        for (int jn = 0; jn < 8; jn++)
            #pragma unroll
            for (int r = 0; r < 4; r++)
                acc[i][jn][r] = __expf(tv * acc[i][jn][r]);

    #pragma unroll
    for (int i = 0; i < 2; i++) {
        #pragma unroll
        for (int h = 0; h < 2; h++) {
            float p = 0.f;
            #pragma unroll
            for (int jn = 0; jn < 8; jn++)
                p += acc[i][jn][h * 2] + acc[i][jn][h * 2 + 1];
            p += __shfl_xor_sync(0xffffffffu, p, 1);
            p += __shfl_xor_sync(0xffffffffu, p, 2);
            if (q == 0) {
                int rr = wm * 32 + i * 16 + h * 8 + g;
                sums[rr * 4 + wn] = p;
            }
        }
    }
    __syncthreads();

    // write rT tiles into SMEM; accumulate per-thread column sums
    char* tb = smem + OFF_BUF;
    float cs[8][2];
    #pragma unroll
    for (int jn = 0; jn < 8; jn++) { cs[jn][0] = 0.f; cs[jn][1] = 0.f; }

    #pragma unroll
    for (int i = 0; i < 2; i++) {
        #pragma unroll
        for (int h = 0; h < 2; h++) {
            int rr = wm * 32 + i * 16 + h * 8 + g;
            size_t gr = nbase + rr;
            bool v = gr < NN;
            float inv = 1.0f / (sums[rr * 4 + 0] + sums[rr * 4 + 1] +
                                sums[rr * 4 + 2] + sums[rr * 4 + 3]);
            int ncl = rr >> 6, nn = rr & 63;
            #pragma unroll
            for (int jn = 0; jn < 8; jn++) {
                #pragma unroll
                for (int cc = 0; cc < 2; cc++) {
                    float e = v ? acc[i][jn][h * 2 + cc] * inv : 0.f;
                    cs[jn][cc] += e;
                    int k = wn * 64 + jn * 8 + q * 2 + cc;
                    int mt = k >> 7, kr = k & 127;
                    uint32_t bo = (mt * 2 + ncl) * 16384 + swz((uint32_t)kr * 128 + nn * 2);
                    __nv_bfloat16 hi = __float2bfloat16(e);
                    *(__nv_bfloat16*)(tb + bo) = hi;
                    *(__nv_bfloat16*)(tb + 65536 + bo) =
                        __float2bfloat16(e - __bfloat162float(hi));
                    if (lastit && v) rout[gr * (size_t)KK + k] = e;
                }
            }
        }
    }

    // reduce column sums over the 8 g-lanes (same k across g)
    #pragma unroll
    for (int jn = 0; jn < 8; jn++)
        #pragma unroll
        for (int cc = 0; cc < 2; cc++) {
            float s = cs[jn][cc];
            s += __shfl_xor_sync(0xffffffffu, s, 4);
            s += __shfl_xor_sync(0xffffffffu, s, 8);
            s += __shfl_xor_sync(0xffffffffu, s, 16);
            cs[jn][cc] = s;
        }
    if (lane < 4) {
        #pragma unroll
        for (int jn = 0; jn < 8; jn++)
            #pragma unroll
            for (int cc = 0; cc < 2; cc++)
                colsum4[wm * 256 + wn * 64 + jn * 8 + q * 2 + cc] = cs[jn][cc];
    }
    __syncthreads();
    if (tid < 256) {
        float t = (colsum4[tid] + colsum4[256 + tid]) +
                  (colsum4[512 + tid] + colsum4[768 + tid]);
        g_rsum_part[rb][tid] = t;
    }

    FENCE_ASYNC();
    if (tid < 8) {
        int arr = tid & 1, t = tid >> 1;
        int mt = t >> 1, ncl = t & 1;
        size_t dsto = ((size_t)mt * NCT + (rb * 2 + ncl)) * 16384;
        char* dst = (arr ? (char*)g_rTlo : (char*)g_rThi) + dsto;
        bulk_st(dst, sb + OFF_BUF + t * 16384 + arr * 65536, 16384);
        BULK_COMMIT();
        BULK_WAIT0();
    }
}

// ---------------------------------------------------------------- GEMM2
// block: 128 clusters x 256 d-cols; 16 warps (4M x 4N), warp 32x64.
__global__ __launch_bounds__(512, 1)
void k_gemm2() {
    extern __shared__ char smem[];
    uint32_t sb = smem_u32(smem);
    const int tid = threadIdx.x;
    const int lane = tid & 31, w = tid >> 5;
    const int wm = w >> 2, wn = w & 3;
    const int mt = blockIdx.x, nt = blockIdx.y, sp = blockIdx.z;
    const uint32_t mb0 = sb + 8, mb1 = sb + 16;

    float acc[2][8][4] = {};

    auto issue = [&](int c, int buf, uint32_t mb) {
        uint32_t st = sb + OFF_BUF + buf * STAGE;
        size_t nc = (size_t)sp * NC2 + c;
        MB_EXPECT(mb, STAGE_TX);
        bulk_ld(st,          (const char*)g_rThi + ((size_t)mt * NCT + nc) * 16384, 16384, mb);
        bulk_ld(st + OFF_AL, (const char*)g_rTlo + ((size_t)mt * NCT + nc) * 16384, 16384, mb);
        bulk_ld(st + OFF_BH, (const char*)g_dThi + ((size_t)nt * NCT + nc) * 32768, 32768, mb);
        bulk_ld(st + OFF_BL, (const char*)g_dTlo + ((size_t)nt * NCT + nc) * 32768, 32768, mb);
    };

    if (tid == 0) {
        MB_INIT(mb0, 1);
        MB_INIT(mb1, 1);
        FENCE_ASYNC();
        issue(0, 0, mb0);
        issue(1, 1, mb1);
    }
    __syncthreads();

    int ph0 = 0, ph1 = 0;
    for (int c = 0; c < NC2; c++) {
        int buf = c & 1;
        uint32_t mb = buf ? mb1 : mb0;
        if (buf == 0) { mbar_wait(mb0, ph0); ph0 ^= 1; }
        else          { mbar_wait(mb1, ph1); ph1 ^= 1; }
        mma_chunk(sb + OFF_BUF + buf * STAGE, acc, lane, wm, wn);
        __syncthreads();
        if (c + 2 < NC2 && tid == 0) { FENCE_ASYNC(); issue(c + 2, buf, mb); }
    }

    // epilogue: 128x256 fp32 partial
    const int g = lane >> 2, q = lane & 3;
    float* p = g_part[sp];
    #pragma unroll
    for (int i = 0; i < 2; i++) {
        #pragma unroll
        for (int h = 0; h < 2; h++) {
            int rr = wm * 32 + i * 16 + h * 8 + g;
            float* dst = p + (size_t)(mt * 128 + rr) * DD + nt * 256 + wn * 64;
            #pragma unroll
            for (int jn = 0; jn < 8; jn++) {
                float2 v = make_float2(acc[i][jn][h * 2], acc[i][jn][h * 2 + 1]);
                *(float2*)(dst + jn * 8 + q * 2) = v;
            }
        }
    }
}

// ---------------------------------------------------------------- finalize mu (fused rsum)
// one block per k: 512 threads reduce g_rsum_part[*][k], then sum partials and divide.
__global__ void k_mu_final(float* __restrict__ extout, int write_ext) {
    int k = blockIdx.x;
    int tid = threadIdx.x;
    float rs = 0.f;
    for (int rb = tid; rb < RB1; rb += 512) rs += g_rsum_part[rb][k];
    #pragma unroll
    for (int off = 16; off > 0; off >>= 1)
        rs += __shfl_xor_sync(0xffffffffu, rs, off);
    __shared__ float ws[16];
    __shared__ float rsum_s;
    if ((tid & 31) == 0) ws[tid >> 5] = rs;
    __syncthreads();
    if (tid == 0) {
        float t = 0.f;
        #pragma unroll
        for (int i = 0; i < 16; i++) t += ws[i];
        rsum_s = t;
    }
    __syncthreads();
    float denom = rsum_s;
    int idx = k * DD + tid;
    float s = 0.f;
    #pragma unroll
    for (int p = 0; p < S2; p++) s += g_part[p][idx];
    float v = s / denom;
    g_mu[idx] = v;
    if (write_ext) extout[idx] = v;
}

// ---------------------------------------------------------------- launch
extern "C" void kernel_launch(void* const* d_in, const int* in_sizes, int n_in,
                              void* d_out, int out_size) {
    const float* embeds = (const float*)d_in[0];
    const float* temp   = (const float*)d_in[1];
    const float* init   = (const float*)d_in[2];
    float* out_mu = (float*)d_out;
    float* out_r  = (float*)d_out + KK * DD;

    cudaFuncSetAttribute(k_gemm1, cudaFuncAttributeMaxDynamicSharedMemorySize, SMEM_TOT);
    cudaFuncSetAttribute(k_gemm2, cudaFuncAttributeMaxDynamicSharedMemorySize, SMEM_TOT);

    // launch order keeps k_gemm1 at launch #4 (ncu capture slot)
    k_norm_split<<<NN + ZBLK, 128>>>(embeds);
    k_transpose<<<dim3(NCT, 2), 256>>>();

    for (int it = 0; it < 11; it++) {
        k_norm_mu<<<KK, 128>>>(init, it == 0 ? 1 : 0);
        k_gemm1<<<RB1, 512, SMEM_TOT>>>(temp, out_r, it == 10 ? 1 : 0);
        k_gemm2<<<dim3(2, 2, S2), 512, SMEM_TOT>>>();
        k_mu_final<<<KK, 512>>>(out_mu, it == 10 ? 1 : 0);
    }
}